// round 2
// baseline (speedup 1.0000x reference)
#include <cuda_runtime.h>

// Spline1DInterpolant, compact-support form.
// s = (x-a)*n/(b-a), ib = floor(s), f = s - ib in [0,1).
// Four contributing coeffs c[ib..ib+3] with closed-form cubic B-spline weights:
//   w0 = (1-f)^3
//   w1 = 4 - 6 f^2 + 3 f^3
//   w2 = 4 - 6 (1-f)^2 + 3 (1-f)^3
//   w3 = f^3
// Vectorized: each thread handles 4 queries (float4 in/out), 16 independent gathers.

__device__ __forceinline__ float eval_one(float s, const float* __restrict__ c, int C) {
    float fib = floorf(s);
    int ib = (int)fib;
    float f = s - fib;          // [0,1)
    float g = 1.0f - f;

    float f2 = f * f, f3 = f2 * f;
    float g2 = g * g, g3 = g2 * g;

    float w0 = g3;
    float w1 = 4.0f - 6.0f * f2 + 3.0f * f3;
    float w2 = 4.0f - 6.0f * g2 + 3.0f * g3;
    float w3 = f3;

    int i0 = max(ib, 0);            // ib >= 0 for x in [a,b] but stay safe
    int i3 = min(ib + 3, C - 1);    // at s == n exactly, c[C] would be OOB with weight 0
    int i1 = min(ib + 1, C - 1);
    int i2 = min(ib + 2, C - 1);

    return c[i0] * w0 + c[i1] * w1 + c[i2] * w2 + c[i3] * w3;
}

__global__ __launch_bounds__(128, 1)
void spline1d_kernel(const float4* __restrict__ x4,
                     const float* __restrict__ a,
                     const float* __restrict__ b,
                     const float* __restrict__ n,
                     const float* __restrict__ c,
                     float4* __restrict__ out4,
                     int B4, int C) {
    int tid = blockIdx.x * blockDim.x + threadIdx.x;
    if (tid >= B4) return;

    float av = a[0];
    float inv_h = n[0] / (b[0] - av);

    float4 xv = x4[tid];
    float s0 = (xv.x - av) * inv_h;
    float s1 = (xv.y - av) * inv_h;
    float s2 = (xv.z - av) * inv_h;
    float s3 = (xv.w - av) * inv_h;

    float4 r;
    r.x = eval_one(s0, c, C);
    r.y = eval_one(s1, c, C);
    r.z = eval_one(s2, c, C);
    r.w = eval_one(s3, c, C);
    out4[tid] = r;
}

extern "C" void kernel_launch(void* const* d_in, const int* in_sizes, int n_in,
                              void* d_out, int out_size) {
    const float* x = (const float*)d_in[0];
    const float* a = (const float*)d_in[1];
    const float* b = (const float*)d_in[2];
    const float* n = (const float*)d_in[3];
    const float* c = (const float*)d_in[4];
    float* out = (float*)d_out;

    int B = in_sizes[0];      // 16384
    int C = in_sizes[4];      // 4096
    int B4 = B / 4;           // 4096 (B divisible by 4)

    int threads = 128;
    int blocks = (B4 + threads - 1) / threads;   // 32
    spline1d_kernel<<<blocks, threads>>>((const float4*)x, a, b, n, c,
                                         (float4*)out, B4, C);
}